// round 17
// baseline (speedup 1.0000x reference)
#include <cuda_runtime.h>
#include <cuda_bf16.h>

#define Bsz   256
#define Tsz   512
#define Tpad  520
#define Csz   128
#define Lsz   64
#define BLANKC 127
#define PF    8
#define RW    34                 // row stride in u32 words (136 B)
#define LN2f  0.69314718055994530942f
#define ESENT (-(1 << 29))

// packed per-(b,t) row: words 0..31 = bf16x2(p_label(2l), p_label(2l+1));
// word 32 = f32 blank prob; word 33 = pad.
__device__ unsigned int g_pk[(size_t)Bsz * Tpad * RW];

// ---------------------------------------------------------------------------
// Kernel 1: softmax per (b,t) row; skip rows t >= input_length[b].
// ---------------------------------------------------------------------------
__global__ __launch_bounds__(128)
void ctc_probs(const float* __restrict__ y_pred,
               const int*   __restrict__ y_true,
               const int*   __restrict__ input_length) {
    const int row  = blockIdx.x * 4 + (threadIdx.x >> 5);   // row = b*512 + t
    const int lane = threadIdx.x & 31;
    const int wid  = (threadIdx.x >> 5);
    const int b = row >> 9;
    const int t = row & 511;
    if (t >= input_length[b]) return;                       // warp-uniform

    __shared__ __align__(16) float sh[4][128];

    const float4 v = reinterpret_cast<const float4*>(y_pred + (size_t)row * Csz)[lane];
    const float e0 = __expf(v.x), e1 = __expf(v.y),
                e2 = __expf(v.z), e3 = __expf(v.w);
    float esum = (e0 + e1) + (e2 + e3);
    #pragma unroll
    for (int o = 16; o; o >>= 1) esum += __shfl_xor_sync(0xffffffffu, esum, o);
    const float inv = __frcp_rn(esum);

    reinterpret_cast<float4*>(sh[wid])[lane] = make_float4(e0, e1, e2, e3);
    __syncwarp();

    const int* yt = y_true + b * Lsz;
    const float p1 = sh[wid][yt[2 * lane]]     * inv;
    const float p3 = sh[wid][yt[2 * lane + 1]] * inv;

    unsigned int* orow = g_pk + ((size_t)b * Tpad + t) * RW;
    const __nv_bfloat162 pk = __floats2bfloat162_rn(p1, p3);  // .x in low half
    orow[lane] = *reinterpret_cast<const unsigned int*>(&pk);
    if (lane == 0) orow[32] = __float_as_uint(sh[wid][BLANKC] * inv);
}

// 2^d, clamped to [-127, 126]; d <= -127 -> exactly 0.0f
__device__ __forceinline__ float wexp2(int d) {
    d = max(min(d, 126), -127);
    return __int_as_float(d * 8388608 + 0x3F800000);
}

// ---------------------------------------------------------------------------
// Kernel 2: fwd-bwd meet-in-the-middle, PER-LANE shared exponent.
// 4 rows/CTA, 8 warps: warp w -> row w>>1, dir w&1; SMSP w&3 hosts TWO
// independent chains (fwd+bwd). R16 showed issue=18%/SMSP at 1 chain --
// pipes have 5x headroom, so the second chain fills empty slots (valid now,
// unlike R14, because the per-lane-exponent math uses ~1/4 the ALU ops).
// ---------------------------------------------------------------------------
__global__ __launch_bounds__(256)
void ctc_ab(const int* __restrict__ y_true,
            const int* __restrict__ input_length,
            const int* __restrict__ label_length,
            float*     __restrict__ out) {
    const int l   = threadIdx.x & 31;
    const int wid = threadIdx.x >> 5;
    const int row = wid >> 1;               // batch row within CTA (0..3)
    const int dir = wid & 1;                // 0 = forward, 1 = backward
    const int b   = blockIdx.x * 4 + row;

    const int Trun  = input_length[b];
    const int Tlast = Trun - 1;
    const int tm    = Tlast >> 1;           // meeting time
    const int ll    = label_length[b];

    const int z1 = y_true[b * Lsz + 2 * l];
    const int z3 = y_true[b * Lsz + 2 * l + 1];
    const unsigned int* base = g_pk + (size_t)b * Tpad * RW;

    __shared__ __align__(16) float4 shBm[4][32];
    __shared__ __align__(16) int    shBE[4][32];
    __shared__ float shBz[4];

    float m0 = 0.f, m1 = 0.f, m2 = 0.f, m3 = 0.f, m4 = 0.f;
    int   E = 0;
    unsigned int xr[PF]; float pr[PF];

    if (dir == 0) {
        // ========================= FORWARD: t = 1..tm =========================
        const bool skip1 = (l > 0) && (z1 != y_true[b * Lsz + max(2 * l - 1, 0)]);
        const float s3w  = (z3 != z1) ? 1.f : 0.f;
        float wb0 = 0.f, wb1 = 0.f;

        if (l == 0) {                       // t=0 init (states 0,1)
            m0 = __uint_as_float(base[32]);
            m1 = __int_as_float(base[0] << 16);
        }

#define RENORM_F() {                                                          \
    const float M = fmaxf(fmaxf(m0, m1), fmaxf(fmaxf(m2, m3), m4));           \
    const int eloc = E + ((__float_as_int(M) >> 23) & 0xFF) - 127;            \
    const int elocN = __shfl_up_sync(0xffffffffu, eloc, 1);                   \
    const int Ef = max(eloc, elocN);                                          \
    const float sc = wexp2(E - Ef);                                           \
    m0 *= sc; m1 *= sc; m2 *= sc; m3 *= sc; m4 *= sc;                         \
    const int EfN = __shfl_up_sync(0xffffffffu, Ef, 1);                       \
    const float w = (l == 0) ? 0.f : wexp2(EfN - Ef);                         \
    wb0 = w; wb1 = skip1 ? w : 0.f;                                           \
    E = Ef; }

        RENORM_F()

        #pragma unroll
        for (int i = 0; i < PF; ++i) {
            xr[i] = base[(1 + i) * RW + l];
            pr[i] = __uint_as_float(base[(1 + i) * RW + 32]);
        }
        const unsigned int* Pl = base + 9 * RW + l;
        const float*        Pb = reinterpret_cast<const float*>(base + 9 * RW + 32);

#define STEP_F(j) {                                                           \
    const unsigned int u = xr[j];                                             \
    const float pbv = pr[j];                                                  \
    xr[j] = Pl[(j) * RW];                                                     \
    pr[j] = Pb[(j) * RW];                                                     \
    const float p1v = __int_as_float(u << 16);                                \
    const float p3v = __int_as_float(u & 0xFFFF0000u);                        \
    const float mN = __shfl_up_sync(0xffffffffu, m3, 1);                      \
    const float t01 = m0 + m1, t12 = m1 + m2;                                 \
    const float t23 = m2 + m3, t34 = m3 + m4;                                 \
    const float nm0 = fmaf(mN, wb0, m0) * pbv;                                \
    const float nm1 = fmaf(mN, wb1, t01) * p1v;                               \
    const float nm2 = t12 * pbv;                                              \
    const float nm3 = fmaf(m1, s3w, t23) * p3v;                               \
    const float nm4 = t34 * pbv;                                              \
    m0 = nm0; m1 = nm1; m2 = nm2; m3 = nm3; m4 = nm4; }

        const int nsteps = tm;
        const int nfull  = nsteps >> 3;
        const int rem    = nsteps & 7;
        for (int c = 0; c < nfull; ++c) {
            #pragma unroll
            for (int j = 0; j < PF; ++j) {
                STEP_F(j)
                if ((j & 3) == 3) RENORM_F()
            }
            Pl += PF * RW; Pb += PF * RW;
        }
        #pragma unroll
        for (int j = 0; j < PF; ++j) {
            if (j < rem) { STEP_F(j) RENORM_F() }
        }
#undef STEP_F
#undef RENORM_F
    } else {
        // ================= BACKWARD: rows T_run-1 down to tm+1 =================
        const float sAw  = (z3 != z1) ? 1.f : 0.f;                   // 4l+1 -> 4l+3
        const bool skipB = (l < 31) && (y_true[b * Lsz + 2 * l + 2] != z3);
        float mz = 0.f;
        float wbA = 0.f, wbB = 0.f;
        {   // init at t = T_run-1: indicator on states {2ll-1, 2ll}
            const int s0 = 4 * l, t1 = 2 * ll - 1, t2 = 2 * ll;
            m0 = (s0     == t1 || s0     == t2) ? 1.f : 0.f;
            m1 = (s0 + 1 == t1 || s0 + 1 == t2) ? 1.f : 0.f;
            m2 = (s0 + 2 == t1 || s0 + 2 == t2) ? 1.f : 0.f;
            m3 = (s0 + 3 == t1 || s0 + 3 == t2) ? 1.f : 0.f;
            mz = (ll == 64) ? 1.f : 0.f;                  // state 128
        }

#define RENORM_B() {                                                          \
    const float M = fmaxf(fmaxf(m0, m1), fmaxf(fmaxf(m2, m3), mz));           \
    const int eloc = E + ((__float_as_int(M) >> 23) & 0xFF) - 127;            \
    const int elocN = __shfl_down_sync(0xffffffffu, eloc, 1);                 \
    const int Ef = max(eloc, elocN);                                          \
    const float sc = wexp2(E - Ef);                                           \
    m0 *= sc; m1 *= sc; m2 *= sc; m3 *= sc; mz *= sc;                         \
    const int EfN = __shfl_down_sync(0xffffffffu, Ef, 1);                     \
    const float w = wexp2(EfN - Ef);                                          \
    wbA = (l == 31) ? 1.f : w;                                                \
    wbB = (skipB)   ? w   : 0.f;                                              \
    E = Ef; }

        RENORM_B()

        #pragma unroll
        for (int i = 0; i < PF; ++i) {
            const int tt = Tlast - i;
            xr[i] = base[(size_t)tt * RW + l];
            pr[i] = __uint_as_float(base[(size_t)tt * RW + 32]);
        }
        const unsigned int* Pl = base + (size_t)(Tlast - 8) * RW + l;
        const float*        Pb = reinterpret_cast<const float*>(
                                     base + (size_t)(Tlast - 8) * RW + 32);

#define STEP_B(j) {                                                           \
    const unsigned int u = xr[j];                                             \
    const float pbv = pr[j];                                                  \
    xr[j] = Pl[-((j) * RW)];                                                  \
    pr[j] = Pb[-((j) * RW)];                                                  \
    const float p1v = __int_as_float(u << 16);                                \
    const float p3v = __int_as_float(u & 0xFFFF0000u);                        \
    const float g0 = m0 * pbv, g1 = m1 * p1v;                                 \
    const float g2 = m2 * pbv, g3 = m3 * p3v;                                 \
    const float gz = mz * pbv;                                                \
    float gA = __shfl_down_sync(0xffffffffu, g0, 1);                          \
    float gB = __shfl_down_sync(0xffffffffu, g1, 1);                          \
    if (l == 31) { gA = gz; gB = 0.f; }                                       \
    const float nm0 = g0 + g1;                                                \
    const float nm1 = fmaf(g3, sAw, g1 + g2);                                 \
    const float nm2 = g2 + g3;                                                \
    const float nm3 = fmaf(gB, wbB, fmaf(gA, wbA, g3));                       \
    mz = gz; m0 = nm0; m1 = nm1; m2 = nm2; m3 = nm3; }

        const int nsteps = Tlast - tm;
        const int nfull  = nsteps >> 3;
        const int rem    = nsteps & 7;
        for (int c = 0; c < nfull; ++c) {
            #pragma unroll
            for (int j = 0; j < PF; ++j) {
                STEP_B(j)
                if ((j & 3) == 3) RENORM_B()
            }
            Pl -= PF * RW; Pb -= PF * RW;
        }
        #pragma unroll
        for (int j = 0; j < PF; ++j) {
            if (j < rem) { STEP_B(j) RENORM_B() }
        }
#undef STEP_B
#undef RENORM_B

        shBm[row][l] = make_float4(m0, m1, m2, m3);
        shBE[row][l] = E;
        if (l == 31) shBz[row] = mz;
    }

    __syncthreads();

    if (dir == 0) {
        // combine: p = sum_s alpha_tm(s) * beta_tm(s)
        const float4 bb = shBm[row][l];
        const int    Eb = shBE[row][l];
        float pm = (m0 * bb.x + m1 * bb.y) + (m2 * bb.z + m3 * bb.w);
        if (l == 31) pm = fmaf(m4, shBz[row], pm);
        int pe = (pm > 0.f) ? (E + Eb) : ESENT;   // mask dead lanes
        int Em = pe;
        #pragma unroll
        for (int o = 16; o; o >>= 1) Em = max(Em, __shfl_xor_sync(0xffffffffu, Em, o));
        float v = pm * wexp2(pe - Em);
        #pragma unroll
        for (int o = 16; o; o >>= 1) v += __shfl_xor_sync(0xffffffffu, v, o);
        if (l == 0) out[b] = -(__logf(v) + (float)Em * LN2f);
    }
}

// ---------------------------------------------------------------------------
extern "C" void kernel_launch(void* const* d_in, const int* in_sizes, int n_in,
                              void* d_out, int out_size) {
    const int*   y_true = nullptr;
    const float* y_pred = nullptr;
    const int*   ilen   = nullptr;
    const int*   llen   = nullptr;
    for (int i = 0; i < n_in; ++i) {
        const int sz = in_sizes[i];
        if (sz == Bsz * Tsz * Csz)      y_pred = (const float*)d_in[i];
        else if (sz == Bsz * Lsz)       y_true = (const int*)d_in[i];
        else if (sz == Bsz) {
            if (!ilen) ilen = (const int*)d_in[i];
            else       llen = (const int*)d_in[i];
        }
    }
    float* out = (float*)d_out;

    ctc_probs<<<(Bsz * Tsz) / 4, 128>>>(y_pred, y_true, ilen);
    ctc_ab<<<Bsz / 4, 256>>>(y_true, ilen, llen, out);
}